// round 1
// baseline (speedup 1.0000x reference)
#include <cuda_runtime.h>
#include <cstdint>
#include <math.h>

#define Bx 32
#define Tt 2048
#define Dd 256
#define Hh 256
#define Gg 512
#define NCTA 4
#define RTH 512

// Scratch (static device globals; no runtime allocation allowed)
__device__ float g_Gx[(size_t)Bx * Tt * Gg];   // x @ Wg_x + bg   [B*T, 512]
__device__ float g_Cx[(size_t)Bx * Tt * Hh];   // x @ Wc_x + bc   [B*T, 256]
__device__ float g_rnn[(size_t)Bx * Tt * Hh];  // GRU hidden outputs

__device__ __forceinline__ float sigmoidf_(float x) { return 1.f / (1.f + __expf(-x)); }

// ---------------------------------------------------------------------------
// Parallel GEMM: out[M,N] = A[M,256] @ W[0:256, N] + bias, optional sigmoid.
// W row stride == N for all three uses (Wg:[512,512], Wc:[512,256], Wp:[256,256]).
// CTA tile 64x64, BK=16, 256 threads, 4x4 per thread, simple global prefetch.
// ---------------------------------------------------------------------------
template <int N, bool SIG>
__global__ void __launch_bounds__(256) gemm_k256(
    const float* __restrict__ A, const float* __restrict__ W,
    const float* __restrict__ bias, float* __restrict__ out)
{
    __shared__ float As[16][64];   // [k][m] (transposed at staging)
    __shared__ float Bs[16][64];   // [k][n]
    const int tid = threadIdx.x;
    const int bm = blockIdx.x * 64;
    const int bn = blockIdx.y * 64;
    const int tx = tid & 15, ty = tid >> 4;
    const int arow = tid >> 2, ak = (tid & 3) * 4;
    const int brow = tid >> 4, bn4 = (tid & 15) * 4;

    float acc[4][4];
#pragma unroll
    for (int i = 0; i < 4; i++)
#pragma unroll
        for (int j = 0; j < 4; j++) acc[i][j] = 0.f;

    const float* aptr = A + (size_t)(bm + arow) * 256 + ak;
    const float* bptr = W + (size_t)brow * N + bn + bn4;

    float4 a4 = *(const float4*)aptr;
    float4 b4 = *(const float4*)bptr;

    for (int k0 = 0; k0 < 256; k0 += 16) {
        As[ak + 0][arow] = a4.x; As[ak + 1][arow] = a4.y;
        As[ak + 2][arow] = a4.z; As[ak + 3][arow] = a4.w;
        *(float4*)&Bs[brow][bn4] = b4;
        __syncthreads();
        if (k0 < 240) {
            a4 = *(const float4*)(aptr + k0 + 16);
            b4 = *(const float4*)(bptr + (size_t)(k0 + 16) * N);
        }
#pragma unroll
        for (int kk = 0; kk < 16; kk++) {
            float4 av = *(const float4*)&As[kk][ty * 4];
            float4 bv = *(const float4*)&Bs[kk][tx * 4];
            float a_[4] = {av.x, av.y, av.z, av.w};
            float b_[4] = {bv.x, bv.y, bv.z, bv.w};
#pragma unroll
            for (int i = 0; i < 4; i++)
#pragma unroll
                for (int j = 0; j < 4; j++) acc[i][j] += a_[i] * b_[j];
        }
        __syncthreads();
    }

    float4 bsv = *(const float4*)&bias[bn + tx * 4];
    float bb[4] = {bsv.x, bsv.y, bsv.z, bsv.w};
#pragma unroll
    for (int i = 0; i < 4; i++) {
        int m = bm + ty * 4 + i;
        float v0 = acc[i][0] + bb[0];
        float v1 = acc[i][1] + bb[1];
        float v2 = acc[i][2] + bb[2];
        float v3 = acc[i][3] + bb[3];
        if (SIG) { v0 = sigmoidf_(v0); v1 = sigmoidf_(v1); v2 = sigmoidf_(v2); v3 = sigmoidf_(v3); }
        *(float4*)&out[(size_t)m * N + bn + tx * 4] = make_float4(v0, v1, v2, v3);
    }
}

// ---------------------------------------------------------------------------
// Sequential recurrence: 32 clusters of 4 CTAs (one cluster per batch row).
// CTA j of a cluster owns gate cols r[j*64..+64), u[256+j*64..+64) and
// candidate/h cols [j*64..+64). Weights (h-part) live in SMEM fp32.
// Per step: gate GEMV -> sigmoid -> exchange r*h slices (DSMEM) -> cluster sync
//           candidate GEMV -> tanh -> h update -> exchange h slices -> sync.
// ---------------------------------------------------------------------------
__device__ __forceinline__ void st_cluster(uint32_t saddr, float v, unsigned rank)
{
    uint32_t ra;
    asm volatile("mapa.shared::cluster.u32 %0, %1, %2;" : "=r"(ra) : "r"(saddr), "r"(rank));
    asm volatile("st.shared::cluster.f32 [%0], %1;" :: "r"(ra), "f"(v) : "memory");
}

__device__ __forceinline__ void cluster_sync_()
{
    asm volatile("barrier.cluster.arrive.aligned;" ::: "memory");
    asm volatile("barrier.cluster.wait.aligned;" ::: "memory");
}

// SMEM float offsets
#define OFF_WG 0          // [256][128]
#define OFF_WC 32768      // [256][64]
#define OFF_H  49152      // [256]
#define OFF_RH 49408      // [256]
#define OFF_P  49664      // partials: gate [16][128], cand [16][64]
#define OFF_US 51712      // [64]
#define SMEM_FLOATS 51776
#define SMEM_BYTES (SMEM_FLOATS * 4)

__global__ void __cluster_dims__(NCTA, 1, 1) __launch_bounds__(RTH, 1)
gru_rec(const float* __restrict__ Wg, const float* __restrict__ Wc)
{
    extern __shared__ float sm[];
    float* sWg = sm + OFF_WG;
    float* sWc = sm + OFF_WC;
    float* sh  = sm + OFF_H;
    float* srh = sm + OFF_RH;
    float* sp  = sm + OFF_P;
    float* sus = sm + OFF_US;

    const int tid = threadIdx.x;
    unsigned rank;
    asm("mov.u32 %0, %%cluster_ctarank;" : "=r"(rank));
    const int j = (int)rank;
    const int b = blockIdx.x >> 2;

    // Load weight slices (h-part rows 256..511)
    for (int idx = tid; idx < 256 * 128; idx += RTH) {
        int row = idx >> 7, lc = idx & 127;
        int gcol = (lc < 64) ? (j * 64 + lc) : (256 + j * 64 + (lc - 64));
        sWg[idx] = Wg[(size_t)(256 + row) * 512 + gcol];
    }
    for (int idx = tid; idx < 256 * 64; idx += RTH) {
        int row = idx >> 6, lc = idx & 63;
        sWc[idx] = Wc[(size_t)(256 + row) * 256 + j * 64 + lc];
    }
    if (tid < 256) sh[tid] = 0.f;
    __syncthreads();
    cluster_sync_();

    const float* gGx = g_Gx + (size_t)b * Tt * Gg;
    const float* gCx = g_Cx + (size_t)b * Tt * Hh;
    float* grnn = g_rnn + (size_t)b * Tt * Hh;

    const int lane = tid & 31;      // col group within warp
    const int q = tid >> 5;         // warp id = row chunk (16 rows), warp-uniform
    const int gxcol = (tid < 64) ? (j * 64 + tid) : (256 + j * 64 + (tid - 64));

    uint32_t rh_addr = 0, h_addr = 0;
    if (tid < 64) {
        rh_addr = (uint32_t)__cvta_generic_to_shared(&srh[j * 64 + tid]);
        h_addr  = (uint32_t)__cvta_generic_to_shared(&sh[j * 64 + tid]);
    }

    for (int t = 0; t < Tt; t++) {
        float gxv = 0.f, cxv = 0.f;
        if (tid < 128) gxv = gGx[(size_t)t * Gg + gxcol];       // latency hidden by GEMV
        if (tid < 64)  cxv = gCx[(size_t)t * Hh + j * 64 + tid];

        // ---- gate GEMV: thread = (rows q*16..+16) x (cols lane*4..+4 of 128)
        {
            float a0 = 0, a1 = 0, a2 = 0, a3 = 0;
            const float* wp = sWg + (q * 16) * 128 + lane * 4;
            const float* hp = sh + q * 16;
#pragma unroll
            for (int i = 0; i < 16; i++) {
                float hv = hp[i];                       // warp broadcast
                float4 w4 = *(const float4*)(wp + i * 128);
                a0 += hv * w4.x; a1 += hv * w4.y; a2 += hv * w4.z; a3 += hv * w4.w;
            }
            *(float4*)&sp[q * 128 + lane * 4] = make_float4(a0, a1, a2, a3);
        }
        __syncthreads();
        if (tid < 128) {
            float s = gxv;
#pragma unroll
            for (int qq = 0; qq < 16; qq++) s += sp[qq * 128 + tid];
            float val = sigmoidf_(s);
            if (tid < 64) {
                float rhv = val * sh[j * 64 + tid];     // r * h (own slice)
#pragma unroll
                for (int p = 0; p < NCTA; p++) st_cluster(rh_addr, rhv, (unsigned)p);
            } else {
                sus[tid - 64] = val;                    // u gate
            }
        }
        cluster_sync_();   // rh fully assembled in every CTA

        // ---- candidate GEMV: warp q rows q*16..+16, lane cols lane*2..+2 of 64
        {
            float c0 = 0, c1 = 0;
            const float* wp = sWc + (q * 16) * 64 + lane * 2;
            const float* rp = srh + q * 16;
#pragma unroll
            for (int i = 0; i < 16; i++) {
                float rv = rp[i];                       // warp broadcast
                float2 w2 = *(const float2*)(wp + i * 64);
                c0 += rv * w2.x; c1 += rv * w2.y;
            }
            *(float2*)&sp[q * 64 + lane * 2] = make_float2(c0, c1);
        }
        __syncthreads();
        if (tid < 64) {
            float s = cxv;
#pragma unroll
            for (int qq = 0; qq < 16; qq++) s += sp[qq * 64 + tid];
            float cv = tanhf(s);
            float hold = sh[j * 64 + tid];
            float u = sus[tid];
            float hn = u * hold + (1.f - u) * cv;
#pragma unroll
            for (int p = 0; p < NCTA; p++) st_cluster(h_addr, hn, (unsigned)p);
            grnn[(size_t)t * Hh + j * 64 + tid] = hn;
        }
        cluster_sync_();   // h replicated in every CTA for next step
    }
}

// ---------------------------------------------------------------------------
extern "C" void kernel_launch(void* const* d_in, const int* in_sizes, int n_in,
                              void* d_out, int out_size)
{
    const float* x  = (const float*)d_in[0];
    const float* Wg = (const float*)d_in[1];
    const float* bg = (const float*)d_in[2];
    const float* Wc = (const float*)d_in[3];
    const float* bc = (const float*)d_in[4];
    const float* Wp = (const float*)d_in[5];
    const float* bp = (const float*)d_in[6];
    float* out = (float*)d_out;

    float *pGx = nullptr, *pCx = nullptr, *prnn = nullptr;
    cudaGetSymbolAddress((void**)&pGx, g_Gx);
    cudaGetSymbolAddress((void**)&pCx, g_Cx);
    cudaGetSymbolAddress((void**)&prnn, g_rnn);
    cudaFuncSetAttribute(gru_rec, cudaFuncAttributeMaxDynamicSharedMemorySize, SMEM_BYTES);

    // Parallel precompute of x-projections (fold biases in)
    gemm_k256<512, false><<<dim3(1024, 8), 256>>>(x, Wg, bg, pGx);
    gemm_k256<256, false><<<dim3(1024, 4), 256>>>(x, Wc, bc, pCx);

    // Sequential recurrence: 32 batch rows x 4-CTA clusters
    gru_rec<<<128, RTH, SMEM_BYTES>>>(Wg, Wc);

    // Projection + sigmoid
    gemm_k256<256, true><<<dim3(1024, 4), 256>>>(prnn, Wp, bp, out);
}

// round 2
// speedup vs baseline: 1.1491x; 1.1491x over previous
#include <cuda_runtime.h>
#include <cstdint>
#include <math.h>

#define Bx 32
#define Tt 2048
#define Dd 256
#define Hh 256
#define Gg 512
#define NCTA 4
#define RTH 512

// Scratch (static device globals; no runtime allocation allowed)
__device__ float g_Gx[(size_t)Bx * Tt * Gg];   // x @ Wg_x + bg   [B*T, 512]
__device__ float g_Cx[(size_t)Bx * Tt * Hh];   // x @ Wc_x + bc   [B*T, 256]
__device__ float g_rnn[(size_t)Bx * Tt * Hh];  // GRU hidden outputs

__device__ __forceinline__ float sigmoidf_(float x) { return 1.f / (1.f + __expf(-x)); }

// ---------------------------------------------------------------------------
// Parallel GEMM: out[M,N] = A[M,256] @ W[0:256, N] + bias, optional sigmoid.
// ---------------------------------------------------------------------------
template <int N, bool SIG>
__global__ void __launch_bounds__(256) gemm_k256(
    const float* __restrict__ A, const float* __restrict__ W,
    const float* __restrict__ bias, float* __restrict__ out)
{
    __shared__ float As[16][64];   // [k][m]
    __shared__ float Bs[16][64];   // [k][n]
    const int tid = threadIdx.x;
    const int bm = blockIdx.x * 64;
    const int bn = blockIdx.y * 64;
    const int tx = tid & 15, ty = tid >> 4;
    const int arow = tid >> 2, ak = (tid & 3) * 4;
    const int brow = tid >> 4, bn4 = (tid & 15) * 4;

    float acc[4][4];
#pragma unroll
    for (int i = 0; i < 4; i++)
#pragma unroll
        for (int j = 0; j < 4; j++) acc[i][j] = 0.f;

    const float* aptr = A + (size_t)(bm + arow) * 256 + ak;
    const float* bptr = W + (size_t)brow * N + bn + bn4;

    float4 a4 = *(const float4*)aptr;
    float4 b4 = *(const float4*)bptr;

    for (int k0 = 0; k0 < 256; k0 += 16) {
        As[ak + 0][arow] = a4.x; As[ak + 1][arow] = a4.y;
        As[ak + 2][arow] = a4.z; As[ak + 3][arow] = a4.w;
        *(float4*)&Bs[brow][bn4] = b4;
        __syncthreads();
        if (k0 < 240) {
            a4 = *(const float4*)(aptr + k0 + 16);
            b4 = *(const float4*)(bptr + (size_t)(k0 + 16) * N);
        }
#pragma unroll
        for (int kk = 0; kk < 16; kk++) {
            float4 av = *(const float4*)&As[kk][ty * 4];
            float4 bv = *(const float4*)&Bs[kk][tx * 4];
            float a_[4] = {av.x, av.y, av.z, av.w};
            float b_[4] = {bv.x, bv.y, bv.z, bv.w};
#pragma unroll
            for (int i = 0; i < 4; i++)
#pragma unroll
                for (int j = 0; j < 4; j++) acc[i][j] += a_[i] * b_[j];
        }
        __syncthreads();
    }

    float4 bsv = *(const float4*)&bias[bn + tx * 4];
    float bb[4] = {bsv.x, bsv.y, bsv.z, bsv.w};
#pragma unroll
    for (int i = 0; i < 4; i++) {
        int m = bm + ty * 4 + i;
        float v0 = acc[i][0] + bb[0];
        float v1 = acc[i][1] + bb[1];
        float v2 = acc[i][2] + bb[2];
        float v3 = acc[i][3] + bb[3];
        if (SIG) { v0 = sigmoidf_(v0); v1 = sigmoidf_(v1); v2 = sigmoidf_(v2); v3 = sigmoidf_(v3); }
        *(float4*)&out[(size_t)m * N + bn + tx * 4] = make_float4(v0, v1, v2, v3);
    }
}

// ---------------------------------------------------------------------------
// Recurrence: 32 clusters x 4 CTAs (one cluster per batch row).
// CTA j owns gate cols {r: j*64..+64, u: 256+j*64..+64} and cand/h cols j*64..+64.
// Weights split: h-rows 0..127 in REGISTERS, h-rows 128..255 in SMEM, so
// register-file BW and the smem crossbar deliver weights concurrently.
// ---------------------------------------------------------------------------
__device__ __forceinline__ void st_cluster(uint32_t saddr, float v, unsigned rank)
{
    uint32_t ra;
    asm volatile("mapa.shared::cluster.u32 %0, %1, %2;" : "=r"(ra) : "r"(saddr), "r"(rank));
    asm volatile("st.shared::cluster.f32 [%0], %1;" :: "r"(ra), "f"(v) : "memory");
}

__device__ __forceinline__ void cluster_sync_()
{
    asm volatile("barrier.cluster.arrive.aligned;" ::: "memory");
    asm volatile("barrier.cluster.wait.aligned;" ::: "memory");
}

// SMEM float offsets
#define OFF_WG2 0                 // gate smem weights [128 rows][128 cols]
#define OFF_WC2 16384             // cand smem weights [128 rows][64 cols]
#define OFF_H   24576             // h [256]
#define OFF_RH  24832             // r*h [256]
#define OFF_PG  25088             // gate partials [16][128]
#define OFF_PC  27136             // cand partials [16][64]
#define OFF_US  28160             // u gate [64]
#define SMEM_FLOATS 28224
#define SMEM_BYTES (SMEM_FLOATS * 4)

__global__ void __cluster_dims__(NCTA, 1, 1) __launch_bounds__(RTH, 1)
gru_rec(const float* __restrict__ Wg, const float* __restrict__ Wc)
{
    extern __shared__ float sm[];
    float* sWg2 = sm + OFF_WG2;
    float* sWc2 = sm + OFF_WC2;
    float* sh   = sm + OFF_H;
    float* srh  = sm + OFF_RH;
    float* spg  = sm + OFF_PG;
    float* spc  = sm + OFF_PC;
    float* sus  = sm + OFF_US;

    const int tid = threadIdx.x;
    unsigned rank;
    asm("mov.u32 %0, %%cluster_ctarank;" : "=r"(rank));
    const int j = (int)rank;
    const int b = blockIdx.x >> 2;
    const int lane = tid & 31;
    const int q = tid >> 5;            // warp id (row-chunk), warp-uniform

    // ---- stage SMEM weight halves (h-rows 128..255)
    for (int idx = tid; idx < 128 * 128; idx += RTH) {
        int r = idx >> 7, lc = idx & 127;
        int gcol = (lc < 64) ? (j * 64 + lc) : (256 + j * 64 + (lc - 64));
        sWg2[idx] = Wg[(size_t)(256 + 128 + r) * 512 + gcol];
    }
    for (int idx = tid; idx < 128 * 64; idx += RTH) {
        int r = idx >> 6, lc = idx & 63;
        sWc2[idx] = Wc[(size_t)(256 + 128 + r) * 256 + j * 64 + lc];
    }
    if (tid < 256) sh[tid] = 0.f;

    // ---- register weight halves (h-rows 0..127): warp q owns rows q*8..+8
    float wg[8][4];                    // gate: cols lane*4..+4 (of 128 local)
    float wc[8][2];                    // cand: cols lane*2..+2 (of 64 local)
    {
        const int lc0 = lane * 4;
#pragma unroll
        for (int i = 0; i < 8; i++) {
            int grow = 256 + q * 8 + i;
#pragma unroll
            for (int c = 0; c < 4; c++) {
                int lc = lc0 + c;
                int gcol = (lc < 64) ? (j * 64 + lc) : (256 + j * 64 + (lc - 64));
                wg[i][c] = Wg[(size_t)grow * 512 + gcol];
            }
#pragma unroll
            for (int c = 0; c < 2; c++)
                wc[i][c] = Wc[(size_t)grow * 256 + j * 64 + lane * 2 + c];
        }
    }
    __syncthreads();
    cluster_sync_();

    const float* gGx = g_Gx + (size_t)b * Tt * Gg;
    const float* gCx = g_Cx + (size_t)b * Tt * Hh;
    float* grnn = g_rnn + (size_t)b * Tt * Hh;

    const int gxcol = (tid < 64) ? (j * 64 + tid) : (256 + j * 64 + (tid - 64));

    uint32_t rh_addr = 0, h_addr = 0;
    if (tid < 64) {
        rh_addr = (uint32_t)__cvta_generic_to_shared(&srh[j * 64 + tid]);
        h_addr  = (uint32_t)__cvta_generic_to_shared(&sh[j * 64 + tid]);
    }

    for (int t = 0; t < Tt; t++) {
        float gxv = 0.f, cxv = 0.f;
        if (tid < 128) gxv = gGx[(size_t)t * Gg + gxcol];
        if (tid < 64)  cxv = gCx[(size_t)t * Hh + j * 64 + tid];

        // ================= gate GEMV =================
        {
            float a0 = 0, a1 = 0, a2 = 0, a3 = 0;
            // register half: h-rows q*8..+8
            float4 hA = *(const float4*)&sh[q * 8];
            float4 hB = *(const float4*)&sh[q * 8 + 4];
            float hr[8] = {hA.x, hA.y, hA.z, hA.w, hB.x, hB.y, hB.z, hB.w};
#pragma unroll
            for (int i = 0; i < 8; i++) {
                a0 += hr[i] * wg[i][0]; a1 += hr[i] * wg[i][1];
                a2 += hr[i] * wg[i][2]; a3 += hr[i] * wg[i][3];
            }
            // smem half: h-rows 128+q*8..+8
            float4 hC = *(const float4*)&sh[128 + q * 8];
            float4 hD = *(const float4*)&sh[128 + q * 8 + 4];
            float hs[8] = {hC.x, hC.y, hC.z, hC.w, hD.x, hD.y, hD.z, hD.w};
            const float* wp = sWg2 + (q * 8) * 128 + lane * 4;
#pragma unroll
            for (int i = 0; i < 8; i++) {
                float4 w4 = *(const float4*)(wp + i * 128);
                a0 += hs[i] * w4.x; a1 += hs[i] * w4.y;
                a2 += hs[i] * w4.z; a3 += hs[i] * w4.w;
            }
            *(float4*)&spg[q * 128 + lane * 4] = make_float4(a0, a1, a2, a3);
        }
        __syncthreads();
        if (tid < 128) {
            float s = gxv;
#pragma unroll
            for (int qq = 0; qq < 16; qq++) s += spg[qq * 128 + tid];
            float val = sigmoidf_(s);
            if (tid < 64) {
                float rhv = val * sh[j * 64 + tid];
#pragma unroll
                for (int p = 0; p < NCTA; p++) st_cluster(rh_addr, rhv, (unsigned)p);
            } else {
                sus[tid - 64] = val;
            }
        }
        cluster_sync_();     // srh assembled everywhere; also orders sus

        // ================= candidate GEMV =================
        {
            float c0 = 0, c1 = 0;
            float4 rA = *(const float4*)&srh[q * 8];
            float4 rB = *(const float4*)&srh[q * 8 + 4];
            float rr[8] = {rA.x, rA.y, rA.z, rA.w, rB.x, rB.y, rB.z, rB.w};
#pragma unroll
            for (int i = 0; i < 8; i++) {
                c0 += rr[i] * wc[i][0]; c1 += rr[i] * wc[i][1];
            }
            float4 rC = *(const float4*)&srh[128 + q * 8];
            float4 rD = *(const float4*)&srh[128 + q * 8 + 4];
            float rs[8] = {rC.x, rC.y, rC.z, rC.w, rD.x, rD.y, rD.z, rD.w};
            const float* wp = sWc2 + (q * 8) * 64 + lane * 2;
#pragma unroll
            for (int i = 0; i < 8; i++) {
                float2 w2 = *(const float2*)(wp + i * 64);
                c0 += rs[i] * w2.x; c1 += rs[i] * w2.y;
            }
            *(float2*)&spc[q * 64 + lane * 2] = make_float2(c0, c1);
        }
        __syncthreads();
        if (tid < 64) {
            float s = cxv;
#pragma unroll
            for (int qq = 0; qq < 16; qq++) s += spc[qq * 64 + tid];
            float cv = tanhf(s);
            float hold = sh[j * 64 + tid];
            float u = sus[tid];
            float hn = u * hold + (1.f - u) * cv;
#pragma unroll
            for (int p = 0; p < NCTA; p++) st_cluster(h_addr, hn, (unsigned)p);
            grnn[(size_t)t * Hh + j * 64 + tid] = hn;
        }
        cluster_sync_();     // h replicated for next step
    }
}

// ---------------------------------------------------------------------------
extern "C" void kernel_launch(void* const* d_in, const int* in_sizes, int n_in,
                              void* d_out, int out_size)
{
    const float* x  = (const float*)d_in[0];
    const float* Wg = (const float*)d_in[1];
    const float* bg = (const float*)d_in[2];
    const float* Wc = (const float*)d_in[3];
    const float* bc = (const float*)d_in[4];
    const float* Wp = (const float*)d_in[5];
    const float* bp = (const float*)d_in[6];
    float* out = (float*)d_out;

    float *pGx = nullptr, *pCx = nullptr, *prnn = nullptr;
    cudaGetSymbolAddress((void**)&pGx, g_Gx);
    cudaGetSymbolAddress((void**)&pCx, g_Cx);
    cudaGetSymbolAddress((void**)&prnn, g_rnn);
    cudaFuncSetAttribute(gru_rec, cudaFuncAttributeMaxDynamicSharedMemorySize, SMEM_BYTES);

    // Parallel precompute of x-projections (fold biases in)
    gemm_k256<512, false><<<dim3(1024, 8), 256>>>(x, Wg, bg, pGx);
    gemm_k256<256, false><<<dim3(1024, 4), 256>>>(x, Wc, bc, pCx);

    // Sequential recurrence: 32 batch rows x 4-CTA clusters
    gru_rec<<<128, RTH, SMEM_BYTES>>>(Wg, Wc);

    // Projection + sigmoid
    gemm_k256<256, true><<<dim3(1024, 4), 256>>>(prnn, Wp, bp, out);
}

// round 3
// speedup vs baseline: 1.2472x; 1.0854x over previous
#include <cuda_runtime.h>
#include <cstdint>
#include <math.h>

#define Bx 32
#define Tt 2048
#define Dd 256
#define Hh 256
#define Gg 512
#define NCTA 4
#define RTH 512

// Scratch (static device globals; no runtime allocation allowed)
__device__ float g_Gx[(size_t)Bx * Tt * Gg];   // x @ Wg_x + bg   [B*T, 512]
__device__ float g_Cx[(size_t)Bx * Tt * Hh];   // x @ Wc_x + bc   [B*T, 256]
__device__ float g_rnn[(size_t)Bx * Tt * Hh];  // GRU hidden outputs

__device__ __forceinline__ float sigmoidf_(float x) { return 1.f / (1.f + __expf(-x)); }

// ---------------------------------------------------------------------------
// Parallel GEMM: out[M,N] = A[M,256] @ W[0:256, N] + bias, optional sigmoid.
// ---------------------------------------------------------------------------
template <int N, bool SIG>
__global__ void __launch_bounds__(256) gemm_k256(
    const float* __restrict__ A, const float* __restrict__ W,
    const float* __restrict__ bias, float* __restrict__ out)
{
    __shared__ float As[16][64];   // [k][m]
    __shared__ float Bs[16][64];   // [k][n]
    const int tid = threadIdx.x;
    const int bm = blockIdx.x * 64;
    const int bn = blockIdx.y * 64;
    const int tx = tid & 15, ty = tid >> 4;
    const int arow = tid >> 2, ak = (tid & 3) * 4;
    const int brow = tid >> 4, bn4 = (tid & 15) * 4;

    float acc[4][4];
#pragma unroll
    for (int i = 0; i < 4; i++)
#pragma unroll
        for (int j = 0; j < 4; j++) acc[i][j] = 0.f;

    const float* aptr = A + (size_t)(bm + arow) * 256 + ak;
    const float* bptr = W + (size_t)brow * N + bn + bn4;

    float4 a4 = *(const float4*)aptr;
    float4 b4 = *(const float4*)bptr;

    for (int k0 = 0; k0 < 256; k0 += 16) {
        As[ak + 0][arow] = a4.x; As[ak + 1][arow] = a4.y;
        As[ak + 2][arow] = a4.z; As[ak + 3][arow] = a4.w;
        *(float4*)&Bs[brow][bn4] = b4;
        __syncthreads();
        if (k0 < 240) {
            a4 = *(const float4*)(aptr + k0 + 16);
            b4 = *(const float4*)(bptr + (size_t)(k0 + 16) * N);
        }
#pragma unroll
        for (int kk = 0; kk < 16; kk++) {
            float4 av = *(const float4*)&As[kk][ty * 4];
            float4 bv = *(const float4*)&Bs[kk][tx * 4];
            float a_[4] = {av.x, av.y, av.z, av.w};
            float b_[4] = {bv.x, bv.y, bv.z, bv.w};
#pragma unroll
            for (int i = 0; i < 4; i++)
#pragma unroll
                for (int j = 0; j < 4; j++) acc[i][j] += a_[i] * b_[j];
        }
        __syncthreads();
    }

    float4 bsv = *(const float4*)&bias[bn + tx * 4];
    float bb[4] = {bsv.x, bsv.y, bsv.z, bsv.w};
#pragma unroll
    for (int i = 0; i < 4; i++) {
        int m = bm + ty * 4 + i;
        float v0 = acc[i][0] + bb[0];
        float v1 = acc[i][1] + bb[1];
        float v2 = acc[i][2] + bb[2];
        float v3 = acc[i][3] + bb[3];
        if (SIG) { v0 = sigmoidf_(v0); v1 = sigmoidf_(v1); v2 = sigmoidf_(v2); v3 = sigmoidf_(v3); }
        *(float4*)&out[(size_t)m * N + bn + tx * 4] = make_float4(v0, v1, v2, v3);
    }
}

// ---------------------------------------------------------------------------
// Recurrence, ROW-partitioned: 32 clusters x 4 CTAs. CTA j owns h rows
// [j*64, j*64+64). Each CTA computes row-partials of BOTH GEMVs over its own
// h slice for ALL output columns, scatters partials to the column owners via
// DSMEM, and owners do a 4-way (gate) / 8-way (cand) reduce. h never leaves
// its owning CTA -> no h broadcast, no r*h exchange.
// Gate weights: 64 registers per thread (thread = one gate column).
// Cand weights: smem, transposed with pad-68 layout (conflict-free LDS128).
// ---------------------------------------------------------------------------
__device__ __forceinline__ void st_cluster(uint32_t saddr, float v, unsigned rank)
{
    uint32_t ra;
    asm volatile("mapa.shared::cluster.u32 %0, %1, %2;" : "=r"(ra) : "r"(saddr), "r"(rank));
    asm volatile("st.shared::cluster.f32 [%0], %1;" :: "r"(ra), "f"(v) : "memory");
}

__device__ __forceinline__ void cluster_sync_()
{
    asm volatile("barrier.cluster.arrive.aligned;" ::: "memory");
    asm volatile("barrier.cluster.wait.aligned;" ::: "memory");
}

// SMEM float offsets
#define OFF_WCT 0                  // cand weights transposed [256 cols][68 pad]
#define OFF_H   17408              // h slice [64]
#define OFF_RH  17472              // r*h slice [64]
#define OFF_U   17536              // u slice [64]
#define OFF_GP  17600              // gate partials [4 src][128]
#define OFF_CP  18112              // cand partials [8 src][64]
#define SMEM_FLOATS 18624
#define SMEM_BYTES (SMEM_FLOATS * 4)

__global__ void __cluster_dims__(NCTA, 1, 1) __launch_bounds__(RTH, 1)
gru_rec(const float* __restrict__ Wg, const float* __restrict__ Wc)
{
    extern __shared__ float sm[];
    float* sWcT = sm + OFF_WCT;
    float* sh   = sm + OFF_H;
    float* srh  = sm + OFF_RH;
    float* su   = sm + OFF_U;
    float* sgp  = sm + OFF_GP;
    float* scp  = sm + OFF_CP;

    const int tid = threadIdx.x;
    unsigned rank;
    asm("mov.u32 %0, %%cluster_ctarank;" : "=r"(rank));
    const int j = (int)rank;
    const int b = blockIdx.x >> 2;

    // ---- gate weight registers: thread tid owns gate column `tid`,
    //      rows 256 + j*64 + i  (i = 0..63)
    float wgr[64];
#pragma unroll
    for (int i = 0; i < 64; i++)
        wgr[i] = Wg[(size_t)(256 + j * 64 + i) * 512 + tid];

    // ---- stage candidate weights transposed: sWcT[c*68 + r] = Wc_h[row r, col c]
    for (int idx = tid; idx < 64 * 256; idx += RTH) {
        int c = idx & 255, r = idx >> 8;
        sWcT[c * 68 + r] = Wc[(size_t)(256 + j * 64 + r) * 256 + c];
    }
    if (tid < 64) sh[tid] = 0.f;
    __syncthreads();
    cluster_sync_();

    const float* gGx = g_Gx + (size_t)b * Tt * Gg;
    const float* gCx = g_Cx + (size_t)b * Tt * Hh;
    float* grnn = g_rnn + (size_t)b * Tt * Hh;

    // gate column -> owner rank + local slot + DSMEM target address
    const int gk = (tid < 256) ? (tid >> 6) : ((tid >> 6) & 3);
    const int gl = (tid < 256) ? (tid & 63) : (64 + (tid & 63));
    const uint32_t gp_addr = (uint32_t)__cvta_generic_to_shared(&sgp[j * 128 + gl]);

    // cand: thread = (col c, row-half s)
    const int c = tid & 255;
    const int s = tid >> 8;
    const int ck = c >> 6;
    const uint32_t cp_addr = (uint32_t)__cvta_generic_to_shared(&scp[(j * 2 + s) * 64 + (c & 63)]);
    const float* wcbase = sWcT + c * 68 + s * 32;
    const float* rhbase = srh + s * 32;

    // gx/cx column indices (reduce side)
    const int gxcol = (tid < 64) ? (j * 64 + tid) : (256 + j * 64 + (tid - 64));

    float gx = (tid < 128) ? gGx[gxcol] : 0.f;
    float cx = (tid < 64)  ? gCx[j * 64 + tid] : 0.f;

    for (int t = 0; t < Tt; t++) {
        // ================= gate partial GEMV (rows_j x all 512 cols) ========
        {
            float a0 = 0.f, a1 = 0.f, a2 = 0.f, a3 = 0.f;
#pragma unroll
            for (int i4 = 0; i4 < 16; i4++) {
                float4 h4 = ((const float4*)sh)[i4];
                a0 += h4.x * wgr[4 * i4 + 0];
                a1 += h4.y * wgr[4 * i4 + 1];
                a2 += h4.z * wgr[4 * i4 + 2];
                a3 += h4.w * wgr[4 * i4 + 3];
            }
            st_cluster(gp_addr, (a0 + a1) + (a2 + a3), (unsigned)gk);
        }
        cluster_sync_();   // gate partials visible at owners

        // ================= gate reduce + r*h (local) ========================
        if (tid < 128) {
            float sv = gx + sgp[tid] + sgp[128 + tid] + sgp[256 + tid] + sgp[384 + tid];
            float val = sigmoidf_(sv);
            if (tid < 64) srh[tid] = val * sh[tid];
            else          su[tid - 64] = val;
        }
        if (tid < 128 && t + 1 < Tt)
            gx = gGx[(size_t)(t + 1) * Gg + gxcol];          // prefetch
        __syncthreads();   // srh ready for all threads

        // ================= cand partial GEMV (32 rows x 256 cols) ===========
        {
            float a0 = 0.f, a1 = 0.f, a2 = 0.f, a3 = 0.f;
#pragma unroll
            for (int i4 = 0; i4 < 8; i4++) {
                float4 r4 = ((const float4*)rhbase)[i4];
                float4 w4 = ((const float4*)wcbase)[i4];
                a0 += r4.x * w4.x;
                a1 += r4.y * w4.y;
                a2 += r4.z * w4.z;
                a3 += r4.w * w4.w;
            }
            st_cluster(cp_addr, (a0 + a1) + (a2 + a3), (unsigned)ck);
        }
        cluster_sync_();   // cand partials visible at owners

        // ================= cand reduce + h update (all local) ===============
        if (tid < 64) {
            float cc = cx;
#pragma unroll
            for (int m = 0; m < 8; m++) cc += scp[m * 64 + tid];
            float cv = tanhf(cc);
            float u = su[tid];
            float hn = u * sh[tid] + (1.f - u) * cv;
            sh[tid] = hn;
            grnn[(size_t)t * Hh + j * 64 + tid] = hn;
        }
        if (tid < 64 && t + 1 < Tt)
            cx = gCx[(size_t)(t + 1) * Hh + j * 64 + tid];   // prefetch
        __syncthreads();   // sh update visible before next gate GEMV
    }
}

// ---------------------------------------------------------------------------
extern "C" void kernel_launch(void* const* d_in, const int* in_sizes, int n_in,
                              void* d_out, int out_size)
{
    const float* x  = (const float*)d_in[0];
    const float* Wg = (const float*)d_in[1];
    const float* bg = (const float*)d_in[2];
    const float* Wc = (const float*)d_in[3];
    const float* bc = (const float*)d_in[4];
    const float* Wp = (const float*)d_in[5];
    const float* bp = (const float*)d_in[6];
    float* out = (float*)d_out;

    float *pGx = nullptr, *pCx = nullptr, *prnn = nullptr;
    cudaGetSymbolAddress((void**)&pGx, g_Gx);
    cudaGetSymbolAddress((void**)&pCx, g_Cx);
    cudaGetSymbolAddress((void**)&prnn, g_rnn);
    cudaFuncSetAttribute(gru_rec, cudaFuncAttributeMaxDynamicSharedMemorySize, SMEM_BYTES);

    // Parallel precompute of x-projections (fold biases in)
    gemm_k256<512, false><<<dim3(1024, 8), 256>>>(x, Wg, bg, pGx);
    gemm_k256<256, false><<<dim3(1024, 4), 256>>>(x, Wc, bc, pCx);

    // Sequential recurrence: 32 batch rows x 4-CTA clusters
    gru_rec<<<128, RTH, SMEM_BYTES>>>(Wg, Wc);

    // Projection + sigmoid
    gemm_k256<256, true><<<dim3(1024, 4), 256>>>(prnn, Wp, bp, out);
}

// round 4
// speedup vs baseline: 1.5562x; 1.2477x over previous
#include <cuda_runtime.h>
#include <cstdint>
#include <math.h>

#define Bx 32
#define Tt 2048
#define Dd 256
#define Hh 256
#define Gg 512
#define NCTA 4
#define RTH 512

// Scratch (static device globals; no runtime allocation allowed)
__device__ float g_Gx[(size_t)Bx * Tt * Gg];   // x @ Wg_x + bg   [B*T, 512]
__device__ float g_Cx[(size_t)Bx * Tt * Hh];   // x @ Wc_x + bc   [B*T, 256]
__device__ float g_rnn[(size_t)Bx * Tt * Hh];  // GRU hidden outputs

__device__ __forceinline__ float sigmoidf_(float x) { return 1.f / (1.f + __expf(-x)); }

// ---------------------------------------------------------------------------
// Parallel GEMM: out[M,N] = A[M,256] @ W[0:256, N] + bias, optional sigmoid.
// ---------------------------------------------------------------------------
template <int N, bool SIG>
__global__ void __launch_bounds__(256) gemm_k256(
    const float* __restrict__ A, const float* __restrict__ W,
    const float* __restrict__ bias, float* __restrict__ out)
{
    __shared__ float As[16][64];   // [k][m]
    __shared__ float Bs[16][64];   // [k][n]
    const int tid = threadIdx.x;
    const int bm = blockIdx.x * 64;
    const int bn = blockIdx.y * 64;
    const int tx = tid & 15, ty = tid >> 4;
    const int arow = tid >> 2, ak = (tid & 3) * 4;
    const int brow = tid >> 4, bn4 = (tid & 15) * 4;

    float acc[4][4];
#pragma unroll
    for (int i = 0; i < 4; i++)
#pragma unroll
        for (int j = 0; j < 4; j++) acc[i][j] = 0.f;

    const float* aptr = A + (size_t)(bm + arow) * 256 + ak;
    const float* bptr = W + (size_t)brow * N + bn + bn4;

    float4 a4 = *(const float4*)aptr;
    float4 b4 = *(const float4*)bptr;

    for (int k0 = 0; k0 < 256; k0 += 16) {
        As[ak + 0][arow] = a4.x; As[ak + 1][arow] = a4.y;
        As[ak + 2][arow] = a4.z; As[ak + 3][arow] = a4.w;
        *(float4*)&Bs[brow][bn4] = b4;
        __syncthreads();
        if (k0 < 240) {
            a4 = *(const float4*)(aptr + k0 + 16);
            b4 = *(const float4*)(bptr + (size_t)(k0 + 16) * N);
        }
#pragma unroll
        for (int kk = 0; kk < 16; kk++) {
            float4 av = *(const float4*)&As[kk][ty * 4];
            float4 bv = *(const float4*)&Bs[kk][tx * 4];
            float a_[4] = {av.x, av.y, av.z, av.w};
            float b_[4] = {bv.x, bv.y, bv.z, bv.w};
#pragma unroll
            for (int i = 0; i < 4; i++)
#pragma unroll
                for (int j = 0; j < 4; j++) acc[i][j] += a_[i] * b_[j];
        }
        __syncthreads();
    }

    float4 bsv = *(const float4*)&bias[bn + tx * 4];
    float bb[4] = {bsv.x, bsv.y, bsv.z, bsv.w};
#pragma unroll
    for (int i = 0; i < 4; i++) {
        int m = bm + ty * 4 + i;
        float v0 = acc[i][0] + bb[0];
        float v1 = acc[i][1] + bb[1];
        float v2 = acc[i][2] + bb[2];
        float v3 = acc[i][3] + bb[3];
        if (SIG) { v0 = sigmoidf_(v0); v1 = sigmoidf_(v1); v2 = sigmoidf_(v2); v3 = sigmoidf_(v3); }
        *(float4*)&out[(size_t)m * N + bn + tx * 4] = make_float4(v0, v1, v2, v3);
    }
}

// ---------------------------------------------------------------------------
// f32x2 packed helpers (sm_103a FFMA2 — only reachable via PTX)
// ---------------------------------------------------------------------------
typedef unsigned long long u64t;
__device__ __forceinline__ u64t pack2_(float lo, float hi)
{ u64t r; asm("mov.b64 %0, {%1, %2};" : "=l"(r) : "f"(lo), "f"(hi)); return r; }
__device__ __forceinline__ void unpack2_(u64t v, float& lo, float& hi)
{ asm("mov.b64 {%0, %1}, %2;" : "=f"(lo), "=f"(hi) : "l"(v)); }
__device__ __forceinline__ u64t fma2_(u64t a, u64t b, u64t c)
{ u64t d; asm("fma.rn.f32x2 %0, %1, %2, %3;" : "=l"(d) : "l"(a), "l"(b), "l"(c)); return d; }

// ---------------------------------------------------------------------------
// mbarrier / DSMEM async-store helpers
// ---------------------------------------------------------------------------
__device__ __forceinline__ uint32_t mapa_(uint32_t saddr, unsigned rank)
{
    uint32_t ra;
    asm volatile("mapa.shared::cluster.u32 %0, %1, %2;" : "=r"(ra) : "r"(saddr), "r"(rank));
    return ra;
}
__device__ __forceinline__ void st_async_tx(uint32_t raddr, float v, uint32_t rmbar)
{
    asm volatile("st.async.shared::cluster.mbarrier::complete_tx::bytes.b32 [%0], %1, [%2];"
                 :: "r"(raddr), "r"(__float_as_uint(v)), "r"(rmbar) : "memory");
}
__device__ __forceinline__ void mbar_init_(uint32_t mbar, uint32_t cnt)
{
    asm volatile("mbarrier.init.shared.b64 [%0], %1;" :: "r"(mbar), "r"(cnt) : "memory");
}
__device__ __forceinline__ void mbar_expect_tx_(uint32_t mbar, uint32_t bytes)
{
    asm volatile("mbarrier.arrive.expect_tx.shared.b64 _, [%0], %1;"
                 :: "r"(mbar), "r"(bytes) : "memory");
}
__device__ __forceinline__ void mbar_wait_parity_(uint32_t mbar, uint32_t parity)
{
    uint32_t done;
    asm volatile(
        "{\n\t.reg .pred p;\n\t"
        "mbarrier.try_wait.parity.acquire.cta.shared::cta.b64 p, [%1], %2;\n\t"
        "selp.b32 %0, 1, 0, p;\n\t}"
        : "=r"(done) : "r"(mbar), "r"(parity) : "memory");
    if (!done) {
        asm volatile(
            "{\n\t.reg .pred P1;\n\t"
            "WL_%=:\n\t"
            "mbarrier.try_wait.parity.acquire.cta.shared::cta.b64 P1, [%0], %1, 0x989680;\n\t"
            "@P1 bra.uni WD_%=;\n\t"
            "bra.uni WL_%=;\n\t"
            "WD_%=:\n\t}"
            :: "r"(mbar), "r"(parity) : "memory");
    }
}
__device__ __forceinline__ void cluster_sync_()
{
    asm volatile("barrier.cluster.arrive.aligned;" ::: "memory");
    asm volatile("barrier.cluster.wait.aligned;" ::: "memory");
}

// SMEM float offsets (keep 8B alignment for all f32x2/mbarrier regions)
#define OFF_WCT 0                  // cand weights transposed [256 cols][66 pad]
#define OFF_H   16896              // h slice [64]
#define OFF_RH  16960              // r*h slice [64]
#define OFF_U   17024              // u slice [64]
#define OFF_GP  17088              // gate partials [4 src][128]
#define OFF_CP  17600              // cand partials [8 src][64]
#define OFF_MB  18112              // 2 mbarriers (2 floats each)
#define SMEM_FLOATS 18120
#define SMEM_BYTES (SMEM_FLOATS * 4)

__global__ void __cluster_dims__(NCTA, 1, 1) __launch_bounds__(RTH, 1)
gru_rec(const float* __restrict__ Wg, const float* __restrict__ Wc)
{
    extern __shared__ float sm[];
    float* sWcT = sm + OFF_WCT;
    float* sh   = sm + OFF_H;
    float* srh  = sm + OFF_RH;
    float* su   = sm + OFF_U;
    float* sgp  = sm + OFF_GP;
    float* scp  = sm + OFF_CP;

    const int tid = threadIdx.x;
    unsigned rank;
    asm("mov.u32 %0, %%cluster_ctarank;" : "=r"(rank));
    const int j = (int)rank;
    const int b = blockIdx.x >> 2;

    const uint32_t gmb = (uint32_t)__cvta_generic_to_shared(sm + OFF_MB);
    const uint32_t cmb = (uint32_t)__cvta_generic_to_shared(sm + OFF_MB + 2);

    if (tid == 0) { mbar_init_(gmb, 1); mbar_init_(cmb, 1); }

    // ---- gate weight registers, packed in row-pairs:
    //      thread owns gate column `tid`; rows 256 + j*64 + (2i, 2i+1)
    u64t wg2[32];
#pragma unroll
    for (int i = 0; i < 32; i++) {
        float w0 = Wg[(size_t)(256 + j * 64 + 2 * i) * 512 + tid];
        float w1 = Wg[(size_t)(256 + j * 64 + 2 * i + 1) * 512 + tid];
        wg2[i] = pack2_(w0, w1);
    }

    // ---- stage candidate weights transposed: sWcT[c*66 + r] = Wc_h[row r, col c]
    for (int idx = tid; idx < 64 * 256; idx += RTH) {
        int c = idx & 255, r = idx >> 8;
        sWcT[c * 66 + r] = Wc[(size_t)(256 + j * 64 + r) * 256 + c];
    }
    if (tid < 64) sh[tid] = 0.f;
    __syncthreads();
    cluster_sync_();   // mbarriers + weights visible cluster-wide before any st.async

    const float* gGx = g_Gx + (size_t)b * Tt * Gg;
    const float* gCx = g_Cx + (size_t)b * Tt * Hh;
    float* grnn = g_rnn + (size_t)b * Tt * Hh;

    // gate column -> owner rank + local slot; precompute remote addrs (loop-invariant)
    const int gk = (tid < 256) ? (tid >> 6) : ((tid >> 6) & 3);
    const int gl = (tid < 256) ? (tid & 63) : (64 + (tid & 63));
    const uint32_t gp_rem  = mapa_((uint32_t)__cvta_generic_to_shared(&sgp[j * 128 + gl]), (unsigned)gk);
    const uint32_t gmb_rem = mapa_(gmb, (unsigned)gk);

    // cand: thread = (col c, row-half s)
    const int c = tid & 255;
    const int s = tid >> 8;
    const int ck = c >> 6;
    const uint32_t cp_rem  = mapa_((uint32_t)__cvta_generic_to_shared(&scp[(j * 2 + s) * 64 + (c & 63)]), (unsigned)ck);
    const uint32_t cmb_rem = mapa_(cmb, (unsigned)ck);
    const float* wcbase = sWcT + c * 66 + s * 32;
    const float* rhbase = srh + s * 32;

    const int gxcol = (tid < 64) ? (j * 64 + tid) : (256 + j * 64 + (tid - 64));

    float gx = (tid < 128) ? gGx[gxcol] : 0.f;
    float cx = (tid < 64)  ? gCx[j * 64 + tid] : 0.f;

    for (int t = 0; t < Tt; t++) {
        const uint32_t ph = (uint32_t)(t & 1);
        if (tid == 0) mbar_expect_tx_(gmb, NCTA * 128 * 4);

        // ===== gate partial GEMV (64 own rows x 1 col), FFMA2 packed ========
        {
            u64t acc2 = 0ull;
            const u64t* hp2 = (const u64t*)sh;
#pragma unroll
            for (int i = 0; i < 32; i++)
                acc2 = fma2_(hp2[i], wg2[i], acc2);
            float lo, hi; unpack2_(acc2, lo, hi);
            st_async_tx(gp_rem, lo + hi, gmb_rem);
        }
        mbar_wait_parity_(gmb, ph);                 // gate partials landed
        if (tid == 0) mbar_expect_tx_(cmb, NCTA * 128 * 4);

        // ===== gate reduce + r*h / u (local) ================================
        if (tid < 128) {
            float sv = gx + sgp[tid] + sgp[128 + tid] + sgp[256 + tid] + sgp[384 + tid];
            float val = sigmoidf_(sv);
            if (tid < 64) srh[tid] = val * sh[tid];
            else          su[tid - 64] = val;
        }
        if (tid < 128 && t + 1 < Tt)
            gx = gGx[(size_t)(t + 1) * Gg + gxcol];          // prefetch
        __syncthreads();   // srh ready for all threads

        // ===== cand partial GEMV (32 rows x 1 col), FFMA2 packed ============
        {
            u64t acc2 = 0ull;
            const u64t* rp2 = (const u64t*)rhbase;
            const u64t* wp2 = (const u64t*)wcbase;
#pragma unroll
            for (int i = 0; i < 16; i++)
                acc2 = fma2_(rp2[i], wp2[i], acc2);
            float lo, hi; unpack2_(acc2, lo, hi);
            st_async_tx(cp_rem, lo + hi, cmb_rem);
        }
        mbar_wait_parity_(cmb, ph);                 // cand partials landed

        // ===== cand reduce + h update (all local) ===========================
        if (tid < 64) {
            float cc = cx;
#pragma unroll
            for (int m = 0; m < 8; m++) cc += scp[m * 64 + tid];
            float cv = tanhf(cc);
            float u = su[tid];
            float hn = u * sh[tid] + (1.f - u) * cv;
            sh[tid] = hn;
            grnn[(size_t)t * Hh + j * 64 + tid] = hn;
        }
        if (tid < 64 && t + 1 < Tt)
            cx = gCx[(size_t)(t + 1) * Hh + j * 64 + tid];   // prefetch
        __syncthreads();   // sh update visible before next gate GEMV
    }
    cluster_sync_();       // keep peers resident until all deliveries consumed
}

// ---------------------------------------------------------------------------
extern "C" void kernel_launch(void* const* d_in, const int* in_sizes, int n_in,
                              void* d_out, int out_size)
{
    const float* x  = (const float*)d_in[0];
    const float* Wg = (const float*)d_in[1];
    const float* bg = (const float*)d_in[2];
    const float* Wc = (const float*)d_in[3];
    const float* bc = (const float*)d_in[4];
    const float* Wp = (const float*)d_in[5];
    const float* bp = (const float*)d_in[6];
    float* out = (float*)d_out;

    float *pGx = nullptr, *pCx = nullptr, *prnn = nullptr;
    cudaGetSymbolAddress((void**)&pGx, g_Gx);
    cudaGetSymbolAddress((void**)&pCx, g_Cx);
    cudaGetSymbolAddress((void**)&prnn, g_rnn);
    cudaFuncSetAttribute(gru_rec, cudaFuncAttributeMaxDynamicSharedMemorySize, SMEM_BYTES);

    // Parallel precompute of x-projections (fold biases in)
    gemm_k256<512, false><<<dim3(1024, 8), 256>>>(x, Wg, bg, pGx);
    gemm_k256<256, false><<<dim3(1024, 4), 256>>>(x, Wc, bc, pCx);

    // Sequential recurrence: 32 batch rows x 4-CTA clusters
    gru_rec<<<128, RTH, SMEM_BYTES>>>(Wg, Wc);

    // Projection + sigmoid
    gemm_k256<256, true><<<dim3(1024, 4), 256>>>(prnn, Wp, bp, out);
}